// round 3
// baseline (speedup 1.0000x reference)
#include <cuda_runtime.h>
#include <math.h>

namespace {

constexpr int BQ   = 256;
constexpr int NSV  = 64;
constexpr int NTRK = 512;
constexpr int H    = 32;
constexpr unsigned FULL = 0xffffffffu;

// ---------------- scratch (static device globals; no allocation) ----------------
__device__ float g_enc_sv [BQ * NSV  * H];
__device__ float g_enc_trk[BQ * NTRK * H];
__device__ float g_enc_pfc[BQ * NTRK * H];
__device__ float g_f1[BQ * NTRK * H];
__device__ float g_f2[BQ * NTRK * H];
__device__ float g_f3[BQ * NTRK * H];
__device__ float g_Wd[H * H];   // W_top - W_bot
__device__ float g_Wb[H * H];   // W_bot

__device__ __forceinline__ float elu_f(float x) {
    return x > 0.f ? x : (__expf(x) - 1.f);
}

// ---------------- weight prep: split conv_W [64,32] ----------------
__global__ void prep_w_k(const float* __restrict__ convW) {
    int i = threadIdx.x;                 // 1024 threads
    float top = convW[i];
    float bot = convW[1024 + i];
    g_Wb[i] = bot;
    g_Wd[i] = top - bot;
}

// ---------------- encoder: y = elu(elu(x@W1+b1)@W2+b2), warp per node ----------------
template<int FIN>
__global__ void __launch_bounds__(256) encode_k(
    const float* __restrict__ x,
    const float* __restrict__ W1, const float* __restrict__ b1,
    const float* __restrict__ W2, const float* __restrict__ b2,
    float* __restrict__ out, int nnode)
{
    __shared__ float sW1[FIN * 32];
    __shared__ float sW2[32 * 32];
    __shared__ float sb1[32], sb2[32];
    int tid = threadIdx.x;
    for (int i = tid; i < FIN * 32; i += 256) sW1[i] = W1[i];
    for (int i = tid; i < 1024;     i += 256) sW2[i] = W2[i];
    if (tid < 32) { sb1[tid] = b1[tid]; sb2[tid] = b2[tid]; }
    __syncthreads();

    int lane = tid & 31, w = tid >> 5;
    int node = blockIdx.x * 8 + w;
    if (node >= nnode) return;

    float xr = (lane < FIN) ? x[node * FIN + lane] : 0.f;
    float h = sb1[lane];
#pragma unroll
    for (int i = 0; i < FIN; i++)
        h = fmaf(__shfl_sync(FULL, xr, i), sW1[i * 32 + lane], h);
    h = elu_f(h);
    float y = sb2[lane];
#pragma unroll
    for (int i = 0; i < 32; i++)
        y = fmaf(__shfl_sync(FULL, h, i), sW2[i * 32 + lane], y);
    y = elu_f(y);
    out[node * 32 + lane] = y;
}

// ---------------- edge conv: kNN(K=8) + factored edge MLP + max-agg ----------------
// One block per event. 256 threads = 8 warps, each warp handles 4 dst nodes/pass.
template<int NS>
__global__ void __launch_bounds__(256) edge_conv_k(
    const float* __restrict__ src,   // [B, NS, 32]
    const float* __restrict__ dst,   // [B, 512, 32]
    const float* __restrict__ bias,  // [32]
    float* __restrict__ out)         // [B, 512, 32]
{
    constexpr int SPL = NS / 32;                 // src slots per lane
    constexpr int TS  = (NS == 512) ? 516 : 65;  // transposed row stride

    extern __shared__ float sh[];
    float* shT    = sh;                 // [32][TS]  transposed src (dim-major)
    float* shRow  = sh + 32 * TS;       // [NS][32]  row-major src
    float* shNorm = shRow + NS * 32;    // [NS]

    const int tid  = threadIdx.x;
    const int lane = tid & 31;
    const int w    = tid >> 5;
    const int b    = blockIdx.x;
    const float* srcB = src + (size_t)b * NS  * 32;
    const float* dstB = dst + (size_t)b * 512 * 32;
    float*       outB = out + (size_t)b * 512 * 32;

    // edge-MLP weight columns in registers (lane = output dim)
    float wd[32], wb[32];
#pragma unroll
    for (int i = 0; i < 32; i++) {
        wd[i] = g_Wd[i * 32 + lane];
        wb[i] = g_Wb[i * 32 + lane];
    }
    const float bj = bias[lane];

    // stage src set: row-major + transposed + norms
    for (int r = w; r < NS; r += 8) {
        float v = srcB[r * 32 + lane];
        shRow[r * 32 + lane] = v;
        shT[lane * TS + r]   = v;
        float s2 = v * v;
#pragma unroll
        for (int o = 16; o; o >>= 1) s2 += __shfl_xor_sync(FULL, s2, o);
        if (lane == 0) shNorm[r] = s2;
    }
    __syncthreads();

    for (int pass = 0; pass < 16; pass++) {
        const int d0 = (pass * 8 + w) * 4;

        float xr[4];
#pragma unroll
        for (int u = 0; u < 4; u++) xr[u] = dstB[(d0 + u) * 32 + lane];

        float acc[4][SPL];
#pragma unroll
        for (int u = 0; u < 4; u++)
#pragma unroll
            for (int t = 0; t < SPL; t++) acc[u][t] = 0.f;

        // ---- dot(dst, src) for all srcs ----
        if constexpr (NS == 512) {
#pragma unroll 4
            for (int d = 0; d < 32; d++) {
                float xd0 = __shfl_sync(FULL, xr[0], d);
                float xd1 = __shfl_sync(FULL, xr[1], d);
                float xd2 = __shfl_sync(FULL, xr[2], d);
                float xd3 = __shfl_sync(FULL, xr[3], d);
                const float* base = &shT[d * TS + 4 * lane];
#pragma unroll
                for (int tp = 0; tp < 4; tp++) {
                    float4 v = *(const float4*)(base + 128 * tp);
                    float vv[4] = {v.x, v.y, v.z, v.w};
#pragma unroll
                    for (int j = 0; j < 4; j++) {
                        acc[0][4 * tp + j] = fmaf(xd0, vv[j], acc[0][4 * tp + j]);
                        acc[1][4 * tp + j] = fmaf(xd1, vv[j], acc[1][4 * tp + j]);
                        acc[2][4 * tp + j] = fmaf(xd2, vv[j], acc[2][4 * tp + j]);
                        acc[3][4 * tp + j] = fmaf(xd3, vv[j], acc[3][4 * tp + j]);
                    }
                }
            }
        } else {
#pragma unroll 4
            for (int d = 0; d < 32; d++) {
                float xd0 = __shfl_sync(FULL, xr[0], d);
                float xd1 = __shfl_sync(FULL, xr[1], d);
                float xd2 = __shfl_sync(FULL, xr[2], d);
                float xd3 = __shfl_sync(FULL, xr[3], d);
#pragma unroll
                for (int t = 0; t < SPL; t++) {
                    float v = shT[d * TS + lane + 32 * t];
                    acc[0][t] = fmaf(xd0, v, acc[0][t]);
                    acc[1][t] = fmaf(xd1, v, acc[1][t]);
                    acc[2][t] = fmaf(xd2, v, acc[2][t]);
                    acc[3][t] = fmaf(xd3, v, acc[3][t]);
                }
            }
        }

        // ---- per dst: top-8 smallest distance, then edge MLP + max ----
#pragma unroll
        for (int u = 0; u < 4; u++) {
            float rv[SPL];
#pragma unroll
            for (int t = 0; t < SPL; t++) {
                int s = (NS == 512) ? (4 * lane + 128 * (t >> 2) + (t & 3))
                                    : (lane + 32 * t);
                rv[t] = shNorm[s] - 2.f * acc[u][t];   // == d2 - ||dst||^2 (rank-equivalent)
            }

            unsigned mask = 0;
            int nb[8];
#pragma unroll
            for (int k = 0; k < 8; k++) {
                float bv = 3.0e38f;
                int   bs = 0x40000000, bt = 0;
#pragma unroll
                for (int t = 0; t < SPL; t++) {
                    int s = (NS == 512) ? (4 * lane + 128 * (t >> 2) + (t & 3))
                                        : (lane + 32 * t);
                    bool free = !((mask >> t) & 1u);
                    bool better = free && (rv[t] < bv || (rv[t] == bv && s < bs));
                    if (better) { bv = rv[t]; bs = s; bt = t; }
                }
                float v = bv; int si = bs;
#pragma unroll
                for (int o = 16; o; o >>= 1) {
                    float ov = __shfl_xor_sync(FULL, v, o);
                    int   oi = __shfl_xor_sync(FULL, si, o);
                    if (ov < v || (ov == v && oi < si)) { v = ov; si = oi; }
                }
                nb[k] = si;
                if (bs == si) mask |= (1u << bt);   // only owning lane matches
            }

            // a_j = b_j + x_i . (Wtop - Wbot)[:,j]   (shared across all 8 neighbors)
            float a = bj;
#pragma unroll
            for (int i = 0; i < 32; i++)
                a = fmaf(__shfl_sync(FULL, xr[u], i), wd[i], a);

            float mm = -3.0e38f;
#pragma unroll
            for (int k = 0; k < 8; k++) {
                const float4* row = (const float4*)&shRow[nb[k] * 32];
                float m = a;
#pragma unroll
                for (int q = 0; q < 8; q++) {
                    float4 v = row[q];
                    m = fmaf(v.x, wb[4 * q + 0], m);
                    m = fmaf(v.y, wb[4 * q + 1], m);
                    m = fmaf(v.z, wb[4 * q + 2], m);
                    m = fmaf(v.w, wb[4 * q + 3], m);
                }
                m = elu_f(m);
                mm = fmaxf(mm, m);
            }
            outB[(d0 + u) * 32 + lane] = mm;
        }
    }
}

// ---------------- mean pool over 512 trk + output MLP + sigmoid ----------------
__global__ void __launch_bounds__(256) pool_out_k(
    const float* __restrict__ f3,
    const float* __restrict__ W1, const float* __restrict__ b1,
    const float* __restrict__ W2, const float* __restrict__ b2,
    float* __restrict__ outF)
{
    __shared__ float part[8][32];
    int tid = threadIdx.x, lane = tid & 31, w = tid >> 5;
    int b = blockIdx.x;
    const float* f = f3 + (size_t)b * 512 * 32;
    float s = 0.f;
    for (int r = w; r < 512; r += 8) s += f[r * 32 + lane];
    part[w][lane] = s;
    __syncthreads();
    if (w == 0) {
        float p = 0.f;
#pragma unroll
        for (int i = 0; i < 8; i++) p += part[i][lane];
        p *= (1.f / 512.f);
        float h = b1[lane];
#pragma unroll
        for (int i = 0; i < 32; i++)
            h = fmaf(__shfl_sync(FULL, p, i), W1[i * 32 + lane], h);
        h = elu_f(h);
        float z = h * W2[lane];
#pragma unroll
        for (int o = 16; o; o >>= 1) z += __shfl_xor_sync(FULL, z, o);
        if (lane == 0) {
            float t = z + b2[0];
            outF[b] = 1.f / (1.f + __expf(-t));
        }
    }
}

// ---------------- second tuple output (arange) handling ----------------
__global__ void tail_k(float* outF, int out_size) {
    int i = threadIdx.x;  // 512 threads
    if (out_size == 768) {
        if (i < 256) {
            long long* p = (long long*)(outF + 256);
            p[i] = (long long)i;
        }
    } else if (out_size > 256) {
        if (i < out_size - 256) outF[256 + i] = (float)i;
    }
}

constexpr int SMEM512 = (32 * 516 + 512 * 32 + 512) * 4;  // 133632 B
constexpr int SMEM64  = (32 * 65  + 64  * 32 + 64 ) * 4;  // 16768 B

} // namespace

extern "C" void kernel_launch(void* const* d_in, const int* in_sizes, int n_in,
                              void* d_out, int out_size)
{
    const float* x_sv   = (const float*)d_in[0];
    const float* x_trk  = (const float*)d_in[1];
    const float* x_pfc  = (const float*)d_in[2];
    // d_in[3..5] = batch indices (implicit, unused)
    const float* sv_W1  = (const float*)d_in[6];
    const float* sv_b1  = (const float*)d_in[7];
    const float* sv_W2  = (const float*)d_in[8];
    const float* sv_b2  = (const float*)d_in[9];
    const float* trk_W1 = (const float*)d_in[10];
    const float* trk_b1 = (const float*)d_in[11];
    const float* trk_W2 = (const float*)d_in[12];
    const float* trk_b2 = (const float*)d_in[13];
    const float* pfc_W1 = (const float*)d_in[14];
    const float* pfc_b1 = (const float*)d_in[15];
    const float* pfc_W2 = (const float*)d_in[16];
    const float* pfc_b2 = (const float*)d_in[17];
    const float* conv_W = (const float*)d_in[18];
    const float* conv_b = (const float*)d_in[19];
    const float* out_W1 = (const float*)d_in[20];
    const float* out_b1 = (const float*)d_in[21];
    const float* out_W2 = (const float*)d_in[22];
    const float* out_b2 = (const float*)d_in[23];

    float *enc_sv, *enc_trk, *enc_pfc, *f1, *f2, *f3;
    cudaGetSymbolAddress((void**)&enc_sv,  g_enc_sv);
    cudaGetSymbolAddress((void**)&enc_trk, g_enc_trk);
    cudaGetSymbolAddress((void**)&enc_pfc, g_enc_pfc);
    cudaGetSymbolAddress((void**)&f1, g_f1);
    cudaGetSymbolAddress((void**)&f2, g_f2);
    cudaGetSymbolAddress((void**)&f3, g_f3);

    cudaFuncSetAttribute(edge_conv_k<512>,
                         cudaFuncAttributeMaxDynamicSharedMemorySize, SMEM512);

    prep_w_k<<<1, 1024>>>(conv_W);
    encode_k<14><<<(BQ * NSV ) / 8, 256>>>(x_sv,  sv_W1,  sv_b1,  sv_W2,  sv_b2,  enc_sv,  BQ * NSV);
    encode_k<30><<<(BQ * NTRK) / 8, 256>>>(x_trk, trk_W1, trk_b1, trk_W2, trk_b2, enc_trk, BQ * NTRK);
    encode_k<10><<<(BQ * NTRK) / 8, 256>>>(x_pfc, pfc_W1, pfc_b1, pfc_W2, pfc_b2, enc_pfc, BQ * NTRK);

    edge_conv_k<64> <<<BQ, 256, SMEM64 >>>(enc_sv,  enc_trk, conv_b, f1);
    edge_conv_k<512><<<BQ, 256, SMEM512>>>(enc_pfc, enc_trk, conv_b, f2);
    edge_conv_k<512><<<BQ, 256, SMEM512>>>(f1,      f2,      conv_b, f3);

    pool_out_k<<<BQ, 256>>>(f3, out_W1, out_b1, out_W2, out_b2, (float*)d_out);
    if (out_size > 256) tail_k<<<1, 512>>>((float*)d_out, out_size);
}

// round 4
// speedup vs baseline: 2.7244x; 2.7244x over previous
#include <cuda_runtime.h>
#include <math.h>

namespace {

constexpr int BQ   = 256;
constexpr int NSV  = 64;
constexpr int NTRK = 512;
constexpr int H    = 32;
constexpr unsigned FULL = 0xffffffffu;

// ---------------- scratch (static device globals; no allocation) ----------------
__device__ float g_enc_sv [BQ * NSV  * H];
__device__ float g_enc_trk[BQ * NTRK * H];
__device__ float g_enc_pfc[BQ * NTRK * H];
__device__ float g_f1[BQ * NTRK * H];
__device__ float g_f2[BQ * NTRK * H];
__device__ float g_f3[BQ * NTRK * H];
__device__ float g_P_sv [BQ * NSV  * H];   // enc_sv  @ Wb
__device__ float g_P_pfc[BQ * NTRK * H];   // enc_pfc @ Wb
__device__ float g_P_f1 [BQ * NTRK * H];   // f1      @ Wb
__device__ float g_A_trk[BQ * NTRK * H];   // enc_trk @ Wd + b
__device__ float g_A_f2 [BQ * NTRK * H];   // f2      @ Wd + b
__device__ float g_Wd[H * H];   // W_top - W_bot
__device__ float g_Wb[H * H];   // W_bot

__device__ __forceinline__ float elu_f(float x) {
    return x > 0.f ? x : (__expf(x) - 1.f);
}

// monotone float -> sortable uint
__device__ __forceinline__ unsigned sortable_u(float v) {
    unsigned u = __float_as_uint(v);
    return (u & 0x80000000u) ? ~u : (u | 0x80000000u);
}

// ---------------- weight prep: split conv_W [64,32] ----------------
__global__ void prep_w_k(const float* __restrict__ convW) {
    int i = threadIdx.x;                 // 1024 threads
    float top = convW[i];
    float bot = convW[1024 + i];
    g_Wb[i] = bot;
    g_Wd[i] = top - bot;
}

// ---------------- encoder: y = elu(elu(x@W1+b1)@W2+b2), warp per node ----------------
template<int FIN>
__global__ void __launch_bounds__(256) encode_k(
    const float* __restrict__ x,
    const float* __restrict__ W1, const float* __restrict__ b1,
    const float* __restrict__ W2, const float* __restrict__ b2,
    float* __restrict__ out, int nnode)
{
    __shared__ float sW1[FIN * 32];
    __shared__ float sW2[32 * 32];
    __shared__ float sb1[32], sb2[32];
    int tid = threadIdx.x;
    for (int i = tid; i < FIN * 32; i += 256) sW1[i] = W1[i];
    for (int i = tid; i < 1024;     i += 256) sW2[i] = W2[i];
    if (tid < 32) { sb1[tid] = b1[tid]; sb2[tid] = b2[tid]; }
    __syncthreads();

    int lane = tid & 31, w = tid >> 5;
    int node = blockIdx.x * 8 + w;
    if (node >= nnode) return;

    float xr = (lane < FIN) ? x[node * FIN + lane] : 0.f;
    float h = sb1[lane];
#pragma unroll
    for (int i = 0; i < FIN; i++)
        h = fmaf(__shfl_sync(FULL, xr, i), sW1[i * 32 + lane], h);
    h = elu_f(h);
    float y = sb2[lane];
#pragma unroll
    for (int i = 0; i < 32; i++)
        y = fmaf(__shfl_sync(FULL, h, i), sW2[i * 32 + lane], y);
    y = elu_f(y);
    out[node * 32 + lane] = y;
}

// ---------------- node projection: P = y@Wb (MODE 0) or A = y@Wd + b (MODE 1) ----------------
template<int MODE>
__global__ void __launch_bounds__(256) proj_k(
    const float* __restrict__ y, const float* __restrict__ conv_b,
    float* __restrict__ out, int nnode)
{
    int tid = threadIdx.x, lane = tid & 31, w = tid >> 5;
    float wcol[32];
    const float* W = MODE ? g_Wd : g_Wb;
#pragma unroll
    for (int i = 0; i < 32; i++) wcol[i] = W[i * 32 + lane];
    float bb = MODE ? conv_b[lane] : 0.f;

    int n0 = (blockIdx.x * 8 + w) * 4;
    if (n0 >= nnode) return;
    float yv[4], ac[4];
#pragma unroll
    for (int u = 0; u < 4; u++) { yv[u] = y[(n0 + u) * 32 + lane]; ac[u] = bb; }
#pragma unroll
    for (int i = 0; i < 32; i++) {
#pragma unroll
        for (int u = 0; u < 4; u++)
            ac[u] = fmaf(__shfl_sync(FULL, yv[u], i), wcol[i], ac[u]);
    }
#pragma unroll
    for (int u = 0; u < 4; u++) out[(n0 + u) * 32 + lane] = ac[u];
}

// ---------------- edge conv: kNN(K=8) + gather of precomputed P + max-agg ----------------
// One block per event. 512 threads = 16 warps, each warp handles 4 dst nodes/pass, 8 passes.
template<int NS>
__global__ void __launch_bounds__(512) edge_conv_k(
    const float* __restrict__ src,   // [B, NS, 32]  (distance features)
    const float* __restrict__ dst,   // [B, 512, 32] (distance features)
    const float* __restrict__ Psrc,  // [B, NS, 32]  src @ Wb
    const float* __restrict__ Adst,  // [B, 512, 32] dst @ Wd + b
    float* __restrict__ out)         // [B, 512, 32]
{
    constexpr int SPL = NS / 32;                 // src slots per lane
    constexpr int TS  = (NS == 512) ? 516 : 65;  // transposed row stride

    extern __shared__ float sh[];
    float* shT    = sh;                 // [32][TS]  transposed src (dim-major)
    float* shP    = sh + 32 * TS;       // [NS][32]  P rows
    float* shNorm = shP + NS * 32;      // [NS]

    const int tid  = threadIdx.x;
    const int lane = tid & 31;
    const int w    = tid >> 5;
    const int b    = blockIdx.x;
    const float* srcB = src  + (size_t)b * NS  * 32;
    const float* dstB = dst  + (size_t)b * 512 * 32;
    const float* PB   = Psrc + (size_t)b * NS  * 32;
    const float* AB   = Adst + (size_t)b * 512 * 32;
    float*       outB = out  + (size_t)b * 512 * 32;

    // stage src set: transposed + P rows + norms
    for (int r = w; r < NS; r += 16) {
        float v = srcB[r * 32 + lane];
        shT[lane * TS + r] = v;
        shP[r * 32 + lane] = PB[r * 32 + lane];
        float s2 = v * v;
#pragma unroll
        for (int o = 16; o; o >>= 1) s2 += __shfl_xor_sync(FULL, s2, o);
        if (lane == 0) shNorm[r] = s2;
    }
    __syncthreads();

    for (int pass = 0; pass < 8; pass++) {
        const int d0 = (pass * 16 + w) * 4;

        float xr[4], a[4];
#pragma unroll
        for (int u = 0; u < 4; u++) {
            xr[u] = dstB[(d0 + u) * 32 + lane];
            a[u]  = AB  [(d0 + u) * 32 + lane];
        }

        float acc[4][SPL];
#pragma unroll
        for (int u = 0; u < 4; u++)
#pragma unroll
            for (int t = 0; t < SPL; t++) acc[u][t] = 0.f;

        // ---- dot(dst, src) for all srcs ----
        if constexpr (NS == 512) {
#pragma unroll 4
            for (int d = 0; d < 32; d++) {
                float xd0 = __shfl_sync(FULL, xr[0], d);
                float xd1 = __shfl_sync(FULL, xr[1], d);
                float xd2 = __shfl_sync(FULL, xr[2], d);
                float xd3 = __shfl_sync(FULL, xr[3], d);
                const float* base = &shT[d * TS + 4 * lane];
#pragma unroll
                for (int tp = 0; tp < 4; tp++) {
                    float4 v = *(const float4*)(base + 128 * tp);
                    float vv[4] = {v.x, v.y, v.z, v.w};
#pragma unroll
                    for (int j = 0; j < 4; j++) {
                        acc[0][4 * tp + j] = fmaf(xd0, vv[j], acc[0][4 * tp + j]);
                        acc[1][4 * tp + j] = fmaf(xd1, vv[j], acc[1][4 * tp + j]);
                        acc[2][4 * tp + j] = fmaf(xd2, vv[j], acc[2][4 * tp + j]);
                        acc[3][4 * tp + j] = fmaf(xd3, vv[j], acc[3][4 * tp + j]);
                    }
                }
            }
        } else {
#pragma unroll 4
            for (int d = 0; d < 32; d++) {
                float xd0 = __shfl_sync(FULL, xr[0], d);
                float xd1 = __shfl_sync(FULL, xr[1], d);
                float xd2 = __shfl_sync(FULL, xr[2], d);
                float xd3 = __shfl_sync(FULL, xr[3], d);
#pragma unroll
                for (int t = 0; t < SPL; t++) {
                    float v = shT[d * TS + lane + 32 * t];
                    acc[0][t] = fmaf(xd0, v, acc[0][t]);
                    acc[1][t] = fmaf(xd1, v, acc[1][t]);
                    acc[2][t] = fmaf(xd2, v, acc[2][t]);
                    acc[3][t] = fmaf(xd3, v, acc[3][t]);
                }
            }
        }

        // ---- convert acc -> sortable keys in place (rv = ||s||^2 - 2<d,s>) ----
#pragma unroll
        for (int t = 0; t < SPL; t++) {
            int s = (NS == 512) ? (4 * lane + 128 * (t >> 2) + (t & 3))
                                : (lane + 32 * t);
            float nv = shNorm[s];
#pragma unroll
            for (int u = 0; u < 4; u++) {
                float rv = fmaf(-2.f, acc[u][t], nv);
                acc[u][t] = __uint_as_float(sortable_u(rv));
            }
        }

        // ---- top-8 via redux-min, interleaved over the 4 dst; gather P + max ----
        float m[4];
#pragma unroll
        for (int u = 0; u < 4; u++) m[u] = -3.0e38f;

#pragma unroll
        for (int k = 0; k < 8; k++) {
#pragma unroll
            for (int u = 0; u < 4; u++) {
                unsigned bk = 0xFFFFFFFFu; int bt = 0;
#pragma unroll
                for (int t = 0; t < SPL; t++) {
                    unsigned kk = __float_as_uint(acc[u][t]);
                    bool lt = kk < bk;       // first-win keeps smallest slot index on ties
                    bk = lt ? kk : bk;
                    bt = lt ? t  : bt;
                }
                unsigned gk = __reduce_min_sync(FULL, bk);
                int s = (NS == 512) ? (4 * lane + 128 * (bt >> 2) + (bt & 3))
                                    : (lane + 32 * bt);
                unsigned cand = (bk == gk) ? (unsigned)s : 0xFFFFFFFFu;
                unsigned gi = __reduce_min_sync(FULL, cand);
                bool won = (bk == gk) && ((unsigned)s == gi);
#pragma unroll
                for (int t = 0; t < SPL; t++)
                    acc[u][t] = (won && t == bt) ? __uint_as_float(0xFFFFFFFFu) : acc[u][t];

                float pj = shP[gi * 32 + lane];   // broadcast row, conflict-free
                m[u] = fmaxf(m[u], elu_f(a[u] + pj));
            }
        }

#pragma unroll
        for (int u = 0; u < 4; u++) outB[(d0 + u) * 32 + lane] = m[u];
    }
}

// ---------------- mean pool over 512 trk + output MLP + sigmoid ----------------
__global__ void __launch_bounds__(256) pool_out_k(
    const float* __restrict__ f3,
    const float* __restrict__ W1, const float* __restrict__ b1,
    const float* __restrict__ W2, const float* __restrict__ b2,
    float* __restrict__ outF)
{
    __shared__ float part[8][32];
    int tid = threadIdx.x, lane = tid & 31, w = tid >> 5;
    int b = blockIdx.x;
    const float* f = f3 + (size_t)b * 512 * 32;
    float s = 0.f;
    for (int r = w; r < 512; r += 8) s += f[r * 32 + lane];
    part[w][lane] = s;
    __syncthreads();
    if (w == 0) {
        float p = 0.f;
#pragma unroll
        for (int i = 0; i < 8; i++) p += part[i][lane];
        p *= (1.f / 512.f);
        float h = b1[lane];
#pragma unroll
        for (int i = 0; i < 32; i++)
            h = fmaf(__shfl_sync(FULL, p, i), W1[i * 32 + lane], h);
        h = elu_f(h);
        float z = h * W2[lane];
#pragma unroll
        for (int o = 16; o; o >>= 1) z += __shfl_xor_sync(FULL, z, o);
        if (lane == 0) {
            float t = z + b2[0];
            outF[b] = 1.f / (1.f + __expf(-t));
        }
    }
}

// ---------------- second tuple output (arange) handling ----------------
__global__ void tail_k(float* outF, int out_size) {
    int i = threadIdx.x;  // 512 threads
    if (out_size == 768) {
        if (i < 256) {
            long long* p = (long long*)(outF + 256);
            p[i] = (long long)i;
        }
    } else if (out_size > 256) {
        if (i < out_size - 256) outF[256 + i] = (float)i;
    }
}

constexpr int SMEM512 = (32 * 516 + 512 * 32 + 512) * 4;  // 133632 B
constexpr int SMEM64  = (32 * 65  + 64  * 32 + 64 ) * 4;  // 16768 B

} // namespace

extern "C" void kernel_launch(void* const* d_in, const int* in_sizes, int n_in,
                              void* d_out, int out_size)
{
    const float* x_sv   = (const float*)d_in[0];
    const float* x_trk  = (const float*)d_in[1];
    const float* x_pfc  = (const float*)d_in[2];
    // d_in[3..5] = batch indices (implicit, unused)
    const float* sv_W1  = (const float*)d_in[6];
    const float* sv_b1  = (const float*)d_in[7];
    const float* sv_W2  = (const float*)d_in[8];
    const float* sv_b2  = (const float*)d_in[9];
    const float* trk_W1 = (const float*)d_in[10];
    const float* trk_b1 = (const float*)d_in[11];
    const float* trk_W2 = (const float*)d_in[12];
    const float* trk_b2 = (const float*)d_in[13];
    const float* pfc_W1 = (const float*)d_in[14];
    const float* pfc_b1 = (const float*)d_in[15];
    const float* pfc_W2 = (const float*)d_in[16];
    const float* pfc_b2 = (const float*)d_in[17];
    const float* conv_W = (const float*)d_in[18];
    const float* conv_b = (const float*)d_in[19];
    const float* out_W1 = (const float*)d_in[20];
    const float* out_b1 = (const float*)d_in[21];
    const float* out_W2 = (const float*)d_in[22];
    const float* out_b2 = (const float*)d_in[23];

    float *enc_sv, *enc_trk, *enc_pfc, *f1, *f2, *f3;
    float *P_sv, *P_pfc, *P_f1, *A_trk, *A_f2;
    cudaGetSymbolAddress((void**)&enc_sv,  g_enc_sv);
    cudaGetSymbolAddress((void**)&enc_trk, g_enc_trk);
    cudaGetSymbolAddress((void**)&enc_pfc, g_enc_pfc);
    cudaGetSymbolAddress((void**)&f1, g_f1);
    cudaGetSymbolAddress((void**)&f2, g_f2);
    cudaGetSymbolAddress((void**)&f3, g_f3);
    cudaGetSymbolAddress((void**)&P_sv,  g_P_sv);
    cudaGetSymbolAddress((void**)&P_pfc, g_P_pfc);
    cudaGetSymbolAddress((void**)&P_f1,  g_P_f1);
    cudaGetSymbolAddress((void**)&A_trk, g_A_trk);
    cudaGetSymbolAddress((void**)&A_f2,  g_A_f2);

    cudaFuncSetAttribute(edge_conv_k<512>,
                         cudaFuncAttributeMaxDynamicSharedMemorySize, SMEM512);

    prep_w_k<<<1, 1024>>>(conv_W);
    encode_k<14><<<(BQ * NSV ) / 8, 256>>>(x_sv,  sv_W1,  sv_b1,  sv_W2,  sv_b2,  enc_sv,  BQ * NSV);
    encode_k<30><<<(BQ * NTRK) / 8, 256>>>(x_trk, trk_W1, trk_b1, trk_W2, trk_b2, enc_trk, BQ * NTRK);
    encode_k<10><<<(BQ * NTRK) / 8, 256>>>(x_pfc, pfc_W1, pfc_b1, pfc_W2, pfc_b2, enc_pfc, BQ * NTRK);

    proj_k<0><<<(BQ * NSV ) / 32, 256>>>(enc_sv,  conv_b, P_sv,  BQ * NSV);
    proj_k<1><<<(BQ * NTRK) / 32, 256>>>(enc_trk, conv_b, A_trk, BQ * NTRK);
    proj_k<0><<<(BQ * NTRK) / 32, 256>>>(enc_pfc, conv_b, P_pfc, BQ * NTRK);

    edge_conv_k<64> <<<BQ, 512, SMEM64 >>>(enc_sv,  enc_trk, P_sv,  A_trk, f1);
    edge_conv_k<512><<<BQ, 512, SMEM512>>>(enc_pfc, enc_trk, P_pfc, A_trk, f2);

    proj_k<0><<<(BQ * NTRK) / 32, 256>>>(f1, conv_b, P_f1, BQ * NTRK);
    proj_k<1><<<(BQ * NTRK) / 32, 256>>>(f2, conv_b, A_f2, BQ * NTRK);

    edge_conv_k<512><<<BQ, 512, SMEM512>>>(f1, f2, P_f1, A_f2, f3);

    pool_out_k<<<BQ, 256>>>(f3, out_W1, out_b1, out_W2, out_b2, (float*)d_out);
    if (out_size > 256) tail_k<<<1, 512>>>((float*)d_out, out_size);
}

// round 5
// speedup vs baseline: 3.0029x; 1.1022x over previous
#include <cuda_runtime.h>
#include <math.h>

namespace {

constexpr int BQ   = 256;
constexpr int NSV  = 64;
constexpr int NTRK = 512;
constexpr int H    = 32;
constexpr unsigned FULL = 0xffffffffu;
typedef unsigned long long u64;

// ---------------- scratch (static device globals; no allocation) ----------------
__device__ float g_enc_sv [BQ * NSV  * H];
__device__ float g_enc_trk[BQ * NTRK * H];
__device__ float g_enc_pfc[BQ * NTRK * H];
__device__ float g_f1[BQ * NTRK * H];
__device__ float g_f2[BQ * NTRK * H];
__device__ float g_f3[BQ * NTRK * H];
__device__ float g_P_sv [BQ * NSV  * H];   // enc_sv  @ Wb
__device__ float g_P_pfc[BQ * NTRK * H];   // enc_pfc @ Wb
__device__ float g_P_f1 [BQ * NTRK * H];   // f1      @ Wb
__device__ float g_A_trk[BQ * NTRK * H];   // enc_trk @ Wd + b
__device__ float g_A_f2 [BQ * NTRK * H];   // f2      @ Wd + b
__device__ float g_Wd[H * H];   // W_top - W_bot
__device__ float g_Wb[H * H];   // W_bot

__device__ __forceinline__ float elu_f(float x) {
    return x > 0.f ? x : (__expf(x) - 1.f);
}

// monotone float -> sortable uint
__device__ __forceinline__ unsigned sortable_u(float v) {
    unsigned u = __float_as_uint(v);
    return (u & 0x80000000u) ? ~u : (u | 0x80000000u);
}

// packed fp32x2 helpers (Blackwell)
__device__ __forceinline__ u64 pack2_dup(float v) {
    u64 r; asm("mov.b64 %0, {%1, %1};" : "=l"(r) : "f"(v)); return r;
}
__device__ __forceinline__ u64 fma2(u64 a, u64 b, u64 c) {
    u64 d; asm("fma.rn.f32x2 %0, %1, %2, %3;" : "=l"(d) : "l"(a), "l"(b), "l"(c)); return d;
}
__device__ __forceinline__ float2 unpack2(u64 v) {
    float2 f; asm("mov.b64 {%0, %1}, %2;" : "=f"(f.x), "=f"(f.y) : "l"(v)); return f;
}

// ---------------- weight prep: split conv_W [64,32] ----------------
__global__ void prep_w_k(const float* __restrict__ convW) {
    int i = threadIdx.x;                 // 1024 threads
    float top = convW[i];
    float bot = convW[1024 + i];
    g_Wb[i] = bot;
    g_Wd[i] = top - bot;
}

// ---------------- encoder: y = elu(elu(x@W1+b1)@W2+b2) ----------------
// 256 thr = 8 warps; warp handles 4 nodes/iter, 4 iters => 128 nodes/block.
// Shared-broadcast LDS replaces SHFL; weights in registers.
template<int FIN>
__global__ void __launch_bounds__(256) encode_k(
    const float* __restrict__ x,
    const float* __restrict__ W1, const float* __restrict__ b1,
    const float* __restrict__ W2, const float* __restrict__ b2,
    float* __restrict__ out)
{
    __shared__ float shX[8][4 * FIN];
    __shared__ float shH[8][4][32];
    int tid = threadIdx.x, lane = tid & 31, w = tid >> 5;

    float w1[FIN], w2[32];
#pragma unroll
    for (int i = 0; i < FIN; i++) w1[i] = W1[i * 32 + lane];
#pragma unroll
    for (int i = 0; i < 32;  i++) w2[i] = W2[i * 32 + lane];
    const float bb1 = b1[lane], bb2 = b2[lane];

    int base = (blockIdx.x * 8 + w) * 16;
#pragma unroll
    for (int it = 0; it < 4; it++) {
        int n0 = base + it * 4;
        for (int i = lane; i < 4 * FIN; i += 32) shX[w][i] = x[n0 * FIN + i];
        __syncwarp();
        float h[4] = {bb1, bb1, bb1, bb1};
#pragma unroll
        for (int i = 0; i < FIN; i++) {
#pragma unroll
            for (int u = 0; u < 4; u++)
                h[u] = fmaf(shX[w][u * FIN + i], w1[i], h[u]);
        }
#pragma unroll
        for (int u = 0; u < 4; u++) { h[u] = elu_f(h[u]); shH[w][u][lane] = h[u]; }
        __syncwarp();
        float y[4] = {bb2, bb2, bb2, bb2};
#pragma unroll
        for (int i = 0; i < 32; i++) {
#pragma unroll
            for (int u = 0; u < 4; u++)
                y[u] = fmaf(shH[w][u][i], w2[i], y[u]);
        }
#pragma unroll
        for (int u = 0; u < 4; u++) out[(n0 + u) * 32 + lane] = elu_f(y[u]);
        __syncwarp();
    }
}

// ---------------- node projection: P = y@Wb (MODE 0) or A = y@Wd + b (MODE 1) ----------------
template<int MODE>
__global__ void __launch_bounds__(256) proj_k(
    const float* __restrict__ y, const float* __restrict__ conv_b,
    float* __restrict__ out)
{
    __shared__ float shY[8][128];
    int tid = threadIdx.x, lane = tid & 31, w = tid >> 5;
    const float* W = MODE ? g_Wd : g_Wb;
    float wcol[32];
#pragma unroll
    for (int i = 0; i < 32; i++) wcol[i] = W[i * 32 + lane];
    const float bb = MODE ? conv_b[lane] : 0.f;

    int base = (blockIdx.x * 8 + w) * 16;
#pragma unroll
    for (int it = 0; it < 4; it++) {
        int n0 = base + it * 4;
        for (int i = lane; i < 128; i += 32) shY[w][i] = y[n0 * 32 + i];
        __syncwarp();
        float ac[4] = {bb, bb, bb, bb};
#pragma unroll
        for (int i = 0; i < 32; i++) {
#pragma unroll
            for (int u = 0; u < 4; u++)
                ac[u] = fmaf(shY[w][u * 32 + i], wcol[i], ac[u]);
        }
#pragma unroll
        for (int u = 0; u < 4; u++) out[(n0 + u) * 32 + lane] = ac[u];
        __syncwarp();
    }
}

// ---------------- edge conv: kNN(K=8) + gather of precomputed P + max-agg ----------------
// One block per event. 512 threads = 16 warps, each warp handles 4 dst/pass, 8 passes.
template<int NS>
__global__ void __launch_bounds__(512) edge_conv_k(
    const float* __restrict__ src,   // [B, NS, 32]  (distance features)
    const float* __restrict__ dst,   // [B, 512, 32] (distance features)
    const float* __restrict__ Psrc,  // [B, NS, 32]  src @ Wb
    const float* __restrict__ Adst,  // [B, 512, 32] dst @ Wd + b
    float* __restrict__ out)         // [B, 512, 32]
{
    constexpr int SPL = NS / 32;                 // src slots per lane
    constexpr int TS  = (NS == 512) ? 516 : 65;  // transposed row stride

    extern __shared__ float sh[];
    float* shT    = sh;                 // [32][TS]  transposed src (dim-major)
    float* shP    = sh + 32 * TS;       // [NS][32]  P rows
    float* shNorm = shP + NS * 32;      // [NS]

    const int tid  = threadIdx.x;
    const int lane = tid & 31;
    const int w    = tid >> 5;
    const int b    = blockIdx.x;
    const float* srcB = src  + (size_t)b * NS  * 32;
    const float* dstB = dst  + (size_t)b * 512 * 32;
    const float* PB   = Psrc + (size_t)b * NS  * 32;
    const float* AB   = Adst + (size_t)b * 512 * 32;
    float*       outB = out  + (size_t)b * 512 * 32;

    // stage src set: transposed + P rows + norms
    for (int r = w; r < NS; r += 16) {
        float v = srcB[r * 32 + lane];
        shT[lane * TS + r] = v;
        shP[r * 32 + lane] = PB[r * 32 + lane];
        float s2 = v * v;
#pragma unroll
        for (int o = 16; o; o >>= 1) s2 += __shfl_xor_sync(FULL, s2, o);
        if (lane == 0) shNorm[r] = s2;
    }
    __syncthreads();

    for (int pass = 0; pass < 8; pass++) {
        const int d0 = (pass * 16 + w) * 4;

        float xr[4], a[4];
#pragma unroll
        for (int u = 0; u < 4; u++) {
            xr[u] = dstB[(d0 + u) * 32 + lane];
            a[u]  = AB  [(d0 + u) * 32 + lane];
        }

        unsigned karr[4][SPL];   // sortable distance keys, slot-indexed

        if constexpr (NS == 512) {
            // ---- packed f32x2 distance accumulation ----
            u64 acc2[4][8];
#pragma unroll
            for (int u = 0; u < 4; u++)
#pragma unroll
                for (int p = 0; p < 8; p++) acc2[u][p] = 0ull;

#pragma unroll 4
            for (int d = 0; d < 32; d++) {
                u64 xp0 = pack2_dup(__shfl_sync(FULL, xr[0], d));
                u64 xp1 = pack2_dup(__shfl_sync(FULL, xr[1], d));
                u64 xp2 = pack2_dup(__shfl_sync(FULL, xr[2], d));
                u64 xp3 = pack2_dup(__shfl_sync(FULL, xr[3], d));
                const float* base = &shT[d * TS + 4 * lane];
#pragma unroll
                for (int tp = 0; tp < 4; tp++) {
                    ulonglong2 vv = *(const ulonglong2*)(base + 128 * tp);
                    acc2[0][2*tp  ] = fma2(xp0, vv.x, acc2[0][2*tp  ]);
                    acc2[0][2*tp+1] = fma2(xp0, vv.y, acc2[0][2*tp+1]);
                    acc2[1][2*tp  ] = fma2(xp1, vv.x, acc2[1][2*tp  ]);
                    acc2[1][2*tp+1] = fma2(xp1, vv.y, acc2[1][2*tp+1]);
                    acc2[2][2*tp  ] = fma2(xp2, vv.x, acc2[2][2*tp  ]);
                    acc2[2][2*tp+1] = fma2(xp2, vv.y, acc2[2][2*tp+1]);
                    acc2[3][2*tp  ] = fma2(xp3, vv.x, acc2[3][2*tp  ]);
                    acc2[3][2*tp+1] = fma2(xp3, vv.y, acc2[3][2*tp+1]);
                }
            }

            // keys: rv = ||s||^2 - 2<d,s>  (rank-equivalent to d2)
#pragma unroll
            for (int tp = 0; tp < 4; tp++) {
#pragma unroll
                for (int hh = 0; hh < 2; hh++) {
                    int s0 = 4 * lane + 128 * tp + 2 * hh;
                    float2 nv = *(const float2*)&shNorm[s0];
                    int t0 = 4 * tp + 2 * hh;
#pragma unroll
                    for (int u = 0; u < 4; u++) {
                        float2 f = unpack2(acc2[u][2 * tp + hh]);
                        karr[u][t0    ] = sortable_u(fmaf(-2.f, f.x, nv.x));
                        karr[u][t0 + 1] = sortable_u(fmaf(-2.f, f.y, nv.y));
                    }
                }
            }
        } else {
            float acc[4][SPL];
#pragma unroll
            for (int u = 0; u < 4; u++)
#pragma unroll
                for (int t = 0; t < SPL; t++) acc[u][t] = 0.f;
#pragma unroll 4
            for (int d = 0; d < 32; d++) {
                float xd0 = __shfl_sync(FULL, xr[0], d);
                float xd1 = __shfl_sync(FULL, xr[1], d);
                float xd2 = __shfl_sync(FULL, xr[2], d);
                float xd3 = __shfl_sync(FULL, xr[3], d);
#pragma unroll
                for (int t = 0; t < SPL; t++) {
                    float v = shT[d * TS + lane + 32 * t];
                    acc[0][t] = fmaf(xd0, v, acc[0][t]);
                    acc[1][t] = fmaf(xd1, v, acc[1][t]);
                    acc[2][t] = fmaf(xd2, v, acc[2][t]);
                    acc[3][t] = fmaf(xd3, v, acc[3][t]);
                }
            }
#pragma unroll
            for (int t = 0; t < SPL; t++) {
                int s = lane + 32 * t;
                float nv = shNorm[s];
#pragma unroll
                for (int u = 0; u < 4; u++)
                    karr[u][t] = sortable_u(fmaf(-2.f, acc[u][t], nv));
            }
        }

        // ---- top-8 via redux-min, interleaved over the 4 dst; gather P + max ----
        float m[4];
#pragma unroll
        for (int u = 0; u < 4; u++) m[u] = -3.0e38f;

#pragma unroll
        for (int k = 0; k < 8; k++) {
#pragma unroll
            for (int u = 0; u < 4; u++) {
                unsigned bk = 0xFFFFFFFFu; int bt = 0;
#pragma unroll
                for (int t = 0; t < SPL; t++) {
                    unsigned kk = karr[u][t];
                    bool lt = kk < bk;       // first-win keeps smallest slot index on ties
                    bk = lt ? kk : bk;
                    bt = lt ? t  : bt;
                }
                unsigned gk = __reduce_min_sync(FULL, bk);
                int s = (NS == 512) ? (4 * lane + 128 * (bt >> 2) + (bt & 3))
                                    : (lane + 32 * bt);
                unsigned cand = (bk == gk) ? (unsigned)s : 0xFFFFFFFFu;
                unsigned gi = __reduce_min_sync(FULL, cand);
                bool won = (bk == gk) && ((unsigned)s == gi);
#pragma unroll
                for (int t = 0; t < SPL; t++)
                    karr[u][t] = (won && t == bt) ? 0xFFFFFFFFu : karr[u][t];

                float pj = shP[gi * 32 + lane];   // broadcast row, conflict-free
                m[u] = fmaxf(m[u], elu_f(a[u] + pj));
            }
        }

#pragma unroll
        for (int u = 0; u < 4; u++) outB[(d0 + u) * 32 + lane] = m[u];
    }
}

// ---------------- mean pool over 512 trk + output MLP + sigmoid ----------------
__global__ void __launch_bounds__(256) pool_out_k(
    const float* __restrict__ f3,
    const float* __restrict__ W1, const float* __restrict__ b1,
    const float* __restrict__ W2, const float* __restrict__ b2,
    float* __restrict__ outF)
{
    __shared__ float part[8][32];
    int tid = threadIdx.x, lane = tid & 31, w = tid >> 5;
    int b = blockIdx.x;
    const float* f = f3 + (size_t)b * 512 * 32;
    float s = 0.f;
    for (int r = w; r < 512; r += 8) s += f[r * 32 + lane];
    part[w][lane] = s;
    __syncthreads();
    if (w == 0) {
        float p = 0.f;
#pragma unroll
        for (int i = 0; i < 8; i++) p += part[i][lane];
        p *= (1.f / 512.f);
        float h = b1[lane];
#pragma unroll
        for (int i = 0; i < 32; i++)
            h = fmaf(__shfl_sync(FULL, p, i), W1[i * 32 + lane], h);
        h = elu_f(h);
        float z = h * W2[lane];
#pragma unroll
        for (int o = 16; o; o >>= 1) z += __shfl_xor_sync(FULL, z, o);
        if (lane == 0) {
            float t = z + b2[0];
            outF[b] = 1.f / (1.f + __expf(-t));
        }
    }
}

// ---------------- second tuple output (arange) handling ----------------
__global__ void tail_k(float* outF, int out_size) {
    int i = threadIdx.x;  // 512 threads
    if (out_size == 768) {
        if (i < 256) {
            long long* p = (long long*)(outF + 256);
            p[i] = (long long)i;
        }
    } else if (out_size > 256) {
        if (i < out_size - 256) outF[256 + i] = (float)i;
    }
}

constexpr int SMEM512 = (32 * 516 + 512 * 32 + 512) * 4;  // 133632 B
constexpr int SMEM64  = (32 * 65  + 64  * 32 + 64 ) * 4;  // 16768 B

} // namespace

extern "C" void kernel_launch(void* const* d_in, const int* in_sizes, int n_in,
                              void* d_out, int out_size)
{
    const float* x_sv   = (const float*)d_in[0];
    const float* x_trk  = (const float*)d_in[1];
    const float* x_pfc  = (const float*)d_in[2];
    // d_in[3..5] = batch indices (implicit, unused)
    const float* sv_W1  = (const float*)d_in[6];
    const float* sv_b1  = (const float*)d_in[7];
    const float* sv_W2  = (const float*)d_in[8];
    const float* sv_b2  = (const float*)d_in[9];
    const float* trk_W1 = (const float*)d_in[10];
    const float* trk_b1 = (const float*)d_in[11];
    const float* trk_W2 = (const float*)d_in[12];
    const float* trk_b2 = (const float*)d_in[13];
    const float* pfc_W1 = (const float*)d_in[14];
    const float* pfc_b1 = (const float*)d_in[15];
    const float* pfc_W2 = (const float*)d_in[16];
    const float* pfc_b2 = (const float*)d_in[17];
    const float* conv_W = (const float*)d_in[18];
    const float* conv_b = (const float*)d_in[19];
    const float* out_W1 = (const float*)d_in[20];
    const float* out_b1 = (const float*)d_in[21];
    const float* out_W2 = (const float*)d_in[22];
    const float* out_b2 = (const float*)d_in[23];

    float *enc_sv, *enc_trk, *enc_pfc, *f1, *f2, *f3;
    float *P_sv, *P_pfc, *P_f1, *A_trk, *A_f2;
    cudaGetSymbolAddress((void**)&enc_sv,  g_enc_sv);
    cudaGetSymbolAddress((void**)&enc_trk, g_enc_trk);
    cudaGetSymbolAddress((void**)&enc_pfc, g_enc_pfc);
    cudaGetSymbolAddress((void**)&f1, g_f1);
    cudaGetSymbolAddress((void**)&f2, g_f2);
    cudaGetSymbolAddress((void**)&f3, g_f3);
    cudaGetSymbolAddress((void**)&P_sv,  g_P_sv);
    cudaGetSymbolAddress((void**)&P_pfc, g_P_pfc);
    cudaGetSymbolAddress((void**)&P_f1,  g_P_f1);
    cudaGetSymbolAddress((void**)&A_trk, g_A_trk);
    cudaGetSymbolAddress((void**)&A_f2,  g_A_f2);

    cudaFuncSetAttribute(edge_conv_k<512>,
                         cudaFuncAttributeMaxDynamicSharedMemorySize, SMEM512);

    prep_w_k<<<1, 1024>>>(conv_W);
    encode_k<14><<<(BQ * NSV ) / 128, 256>>>(x_sv,  sv_W1,  sv_b1,  sv_W2,  sv_b2,  enc_sv);
    encode_k<30><<<(BQ * NTRK) / 128, 256>>>(x_trk, trk_W1, trk_b1, trk_W2, trk_b2, enc_trk);
    encode_k<10><<<(BQ * NTRK) / 128, 256>>>(x_pfc, pfc_W1, pfc_b1, pfc_W2, pfc_b2, enc_pfc);

    proj_k<0><<<(BQ * NSV ) / 128, 256>>>(enc_sv,  conv_b, P_sv);
    proj_k<1><<<(BQ * NTRK) / 128, 256>>>(enc_trk, conv_b, A_trk);
    proj_k<0><<<(BQ * NTRK) / 128, 256>>>(enc_pfc, conv_b, P_pfc);

    edge_conv_k<64> <<<BQ, 512, SMEM64 >>>(enc_sv,  enc_trk, P_sv,  A_trk, f1);
    edge_conv_k<512><<<BQ, 512, SMEM512>>>(enc_pfc, enc_trk, P_pfc, A_trk, f2);

    proj_k<0><<<(BQ * NTRK) / 128, 256>>>(f1, conv_b, P_f1);
    proj_k<1><<<(BQ * NTRK) / 128, 256>>>(f2, conv_b, A_f2);

    edge_conv_k<512><<<BQ, 512, SMEM512>>>(f1, f2, P_f1, A_f2, f3);

    pool_out_k<<<BQ, 256>>>(f3, out_W1, out_b1, out_W2, out_b2, (float*)d_out);
    if (out_size > 256) tail_k<<<1, 512>>>((float*)d_out, out_size);
}

// round 6
// speedup vs baseline: 3.3188x; 1.1052x over previous
#include <cuda_runtime.h>
#include <math.h>

namespace {

constexpr int BQ   = 256;
constexpr int NSV  = 64;
constexpr int NTRK = 512;
constexpr int H    = 32;
constexpr unsigned FULL = 0xffffffffu;
typedef unsigned long long u64;

// ---------------- scratch (static device globals; no allocation) ----------------
__device__ float g_enc_sv [BQ * NSV  * H];
__device__ float g_enc_trk[BQ * NTRK * H];
__device__ float g_enc_pfc[BQ * NTRK * H];
__device__ float g_f1[BQ * NTRK * H];
__device__ float g_f2[BQ * NTRK * H];
__device__ float g_f3[BQ * NTRK * H];
__device__ float g_P_sv [BQ * NSV  * H];   // enc_sv  @ Wb
__device__ float g_P_pfc[BQ * NTRK * H];   // enc_pfc @ Wb
__device__ float g_P_f1 [BQ * NTRK * H];   // f1      @ Wb
__device__ float g_A_trk[BQ * NTRK * H];   // enc_trk @ Wd + b
__device__ float g_A_f2 [BQ * NTRK * H];   // f2      @ Wd + b
__device__ float g_Wd[H * H];   // W_top - W_bot
__device__ float g_Wb[H * H];   // W_bot

__device__ __forceinline__ float elu_f(float x) {
    return x > 0.f ? x : (__expf(x) - 1.f);
}

// monotone float -> sortable uint
__device__ __forceinline__ unsigned sortable_u(float v) {
    unsigned u = __float_as_uint(v);
    return (u & 0x80000000u) ? ~u : (u | 0x80000000u);
}

// packed fp32x2 helpers (Blackwell)
__device__ __forceinline__ u64 pack2_dup(float v) {
    u64 r; asm("mov.b64 %0, {%1, %1};" : "=l"(r) : "f"(v)); return r;
}
__device__ __forceinline__ u64 fma2(u64 a, u64 b, u64 c) {
    u64 d; asm("fma.rn.f32x2 %0, %1, %2, %3;" : "=l"(d) : "l"(a), "l"(b), "l"(c)); return d;
}
__device__ __forceinline__ float2 unpack2(u64 v) {
    float2 f; asm("mov.b64 {%0, %1}, %2;" : "=f"(f.x), "=f"(f.y) : "l"(v)); return f;
}

// ---------------- weight prep: split conv_W [64,32] ----------------
__global__ void prep_w_k(const float* __restrict__ convW) {
    int i = threadIdx.x;                 // 1024 threads
    float top = convW[i];
    float bot = convW[1024 + i];
    g_Wb[i] = bot;
    g_Wd[i] = top - bot;
}

// ---------------- encoder body: y = elu(elu(x@W1+b1)@W2+b2) ----------------
// 256 thr = 8 warps; warp handles 4 nodes/iter, 4 iters => 128 nodes/block.
template<int FIN>
__device__ __forceinline__ void encode_body(
    const float* __restrict__ x,
    const float* __restrict__ W1, const float* __restrict__ b1,
    const float* __restrict__ W2, const float* __restrict__ b2,
    float* __restrict__ out, int blk,
    float (*shX)[120], float (*shH)[4][32])
{
    int tid = threadIdx.x, lane = tid & 31, w = tid >> 5;

    float w1[FIN], w2[32];
#pragma unroll
    for (int i = 0; i < FIN; i++) w1[i] = W1[i * 32 + lane];
#pragma unroll
    for (int i = 0; i < 32;  i++) w2[i] = W2[i * 32 + lane];
    const float bb1 = b1[lane], bb2 = b2[lane];

    int base = (blk * 8 + w) * 16;
#pragma unroll
    for (int it = 0; it < 4; it++) {
        int n0 = base + it * 4;
        for (int i = lane; i < 4 * FIN; i += 32) shX[w][i] = x[n0 * FIN + i];
        __syncwarp();
        float h[4] = {bb1, bb1, bb1, bb1};
#pragma unroll
        for (int i = 0; i < FIN; i++) {
#pragma unroll
            for (int u = 0; u < 4; u++)
                h[u] = fmaf(shX[w][u * FIN + i], w1[i], h[u]);
        }
#pragma unroll
        for (int u = 0; u < 4; u++) { h[u] = elu_f(h[u]); shH[w][u][lane] = h[u]; }
        __syncwarp();
        float y[4] = {bb2, bb2, bb2, bb2};
#pragma unroll
        for (int i = 0; i < 32; i++) {
#pragma unroll
            for (int u = 0; u < 4; u++)
                y[u] = fmaf(shH[w][u][i], w2[i], y[u]);
        }
#pragma unroll
        for (int u = 0; u < 4; u++) out[(n0 + u) * 32 + lane] = elu_f(y[u]);
        __syncwarp();
    }
}

// merged encoder: [0,1024) trk FIN30, [1024,2048) pfc FIN10, [2048,2176) sv FIN14
__global__ void __launch_bounds__(256) encode_all_k(
    const float* __restrict__ x_trk, const float* __restrict__ tW1, const float* __restrict__ tb1,
    const float* __restrict__ tW2, const float* __restrict__ tb2,
    const float* __restrict__ x_pfc, const float* __restrict__ pW1, const float* __restrict__ pb1,
    const float* __restrict__ pW2, const float* __restrict__ pb2,
    const float* __restrict__ x_sv, const float* __restrict__ sW1, const float* __restrict__ sb1,
    const float* __restrict__ sW2, const float* __restrict__ sb2,
    float* __restrict__ enc_trk, float* __restrict__ enc_pfc, float* __restrict__ enc_sv)
{
    __shared__ float shX[8][120];
    __shared__ float shH[8][4][32];
    int b = blockIdx.x;
    if (b < 1024)
        encode_body<30>(x_trk, tW1, tb1, tW2, tb2, enc_trk, b, shX, shH);
    else if (b < 2048)
        encode_body<10>(x_pfc, pW1, pb1, pW2, pb2, enc_pfc, b - 1024, shX, shH);
    else
        encode_body<14>(x_sv, sW1, sb1, sW2, sb2, enc_sv, b - 2048, shX, shH);
}

// ---------------- node projection body: P = y@Wb (MODE 0) or A = y@Wd + b (MODE 1) ----------------
template<int MODE>
__device__ __forceinline__ void proj_body(
    const float* __restrict__ y, const float* __restrict__ conv_b,
    float* __restrict__ out, int blk, float (*shY)[128])
{
    int tid = threadIdx.x, lane = tid & 31, w = tid >> 5;
    const float* W = MODE ? g_Wd : g_Wb;
    float wcol[32];
#pragma unroll
    for (int i = 0; i < 32; i++) wcol[i] = W[i * 32 + lane];
    const float bb = MODE ? conv_b[lane] : 0.f;

    int base = (blk * 8 + w) * 16;
#pragma unroll
    for (int it = 0; it < 4; it++) {
        int n0 = base + it * 4;
        for (int i = lane; i < 128; i += 32) shY[w][i] = y[n0 * 32 + i];
        __syncwarp();
        float ac[4] = {bb, bb, bb, bb};
#pragma unroll
        for (int i = 0; i < 32; i++) {
#pragma unroll
            for (int u = 0; u < 4; u++)
                ac[u] = fmaf(shY[w][u * 32 + i], wcol[i], ac[u]);
        }
#pragma unroll
        for (int u = 0; u < 4; u++) out[(n0 + u) * 32 + lane] = ac[u];
        __syncwarp();
    }
}

// stage-1 merged proj: [0,1024) A_trk, [1024,2048) P_pfc, [2048,2176) P_sv
__global__ void __launch_bounds__(256) proj1_k(
    const float* __restrict__ enc_trk, const float* __restrict__ enc_pfc,
    const float* __restrict__ enc_sv, const float* __restrict__ conv_b,
    float* __restrict__ A_trk, float* __restrict__ P_pfc, float* __restrict__ P_sv)
{
    __shared__ float shY[8][128];
    int b = blockIdx.x;
    if (b < 1024)       proj_body<1>(enc_trk, conv_b, A_trk, b, shY);
    else if (b < 2048)  proj_body<0>(enc_pfc, conv_b, P_pfc, b - 1024, shY);
    else                proj_body<0>(enc_sv,  conv_b, P_sv,  b - 2048, shY);
}

// stage-2 merged proj: [0,1024) P_f1, [1024,2048) A_f2
__global__ void __launch_bounds__(256) proj2_k(
    const float* __restrict__ f1, const float* __restrict__ f2,
    const float* __restrict__ conv_b,
    float* __restrict__ P_f1, float* __restrict__ A_f2)
{
    __shared__ float shY[8][128];
    int b = blockIdx.x;
    if (b < 1024) proj_body<0>(f1, conv_b, P_f1, b, shY);
    else          proj_body<1>(f2, conv_b, A_f2, b - 1024, shY);
}

// ---------------- edge conv body: kNN(K=8) + gather of precomputed P + max-agg ----------------
// 640 threads = 20 warps, each warp handles 2 dst/pass, 13 passes (last partial).
template<int NS>
__device__ __forceinline__ void edge_conv_body(
    const float* __restrict__ srcB, const float* __restrict__ dstB,
    const float* __restrict__ PB,   const float* __restrict__ AB,
    float* __restrict__ outB, float* sh)
{
    constexpr int SPL = NS / 32;                 // src slots per lane
    constexpr int TS  = (NS == 512) ? 516 : 65;  // transposed row stride

    float* shT    = sh;                 // [32][TS]  transposed src (dim-major)
    float* shP    = sh + 32 * TS;       // [NS][32]  P rows
    float* shNorm = shP + NS * 32;      // [NS]

    const int tid  = threadIdx.x;
    const int lane = tid & 31;
    const int w    = tid >> 5;          // 0..19

    // stage src set: transposed + P rows + norms
    for (int r = w; r < NS; r += 20) {
        float v = srcB[r * 32 + lane];
        shT[lane * TS + r] = v;
        shP[r * 32 + lane] = PB[r * 32 + lane];
        float s2 = v * v;
#pragma unroll
        for (int o = 16; o; o >>= 1) s2 += __shfl_xor_sync(FULL, s2, o);
        if (lane == 0) shNorm[r] = s2;
    }
    __syncthreads();

    for (int pass = 0; pass < 13; pass++) {
        const int g0 = pass * 20 + w;
        if (g0 >= 256) break;           // uniform per warp; no syncthreads below
        const int d0 = g0 * 2;

        float xr[2], a[2];
#pragma unroll
        for (int u = 0; u < 2; u++) {
            xr[u] = dstB[(d0 + u) * 32 + lane];
            a[u]  = AB  [(d0 + u) * 32 + lane];
        }

        unsigned karr[2][SPL];   // sortable distance keys, slot-indexed

        if constexpr (NS == 512) {
            // ---- packed f32x2 distance accumulation ----
            u64 acc2[2][8];
#pragma unroll
            for (int u = 0; u < 2; u++)
#pragma unroll
                for (int p = 0; p < 8; p++) acc2[u][p] = 0ull;

#pragma unroll 4
            for (int d = 0; d < 32; d++) {
                u64 xp0 = pack2_dup(__shfl_sync(FULL, xr[0], d));
                u64 xp1 = pack2_dup(__shfl_sync(FULL, xr[1], d));
                const float* base = &shT[d * TS + 4 * lane];
#pragma unroll
                for (int tp = 0; tp < 4; tp++) {
                    ulonglong2 vv = *(const ulonglong2*)(base + 128 * tp);
                    acc2[0][2*tp  ] = fma2(xp0, vv.x, acc2[0][2*tp  ]);
                    acc2[0][2*tp+1] = fma2(xp0, vv.y, acc2[0][2*tp+1]);
                    acc2[1][2*tp  ] = fma2(xp1, vv.x, acc2[1][2*tp  ]);
                    acc2[1][2*tp+1] = fma2(xp1, vv.y, acc2[1][2*tp+1]);
                }
            }

            // keys: rv = ||s||^2 - 2<d,s>  (rank-equivalent to d2)
#pragma unroll
            for (int tp = 0; tp < 4; tp++) {
#pragma unroll
                for (int hh = 0; hh < 2; hh++) {
                    int s0 = 4 * lane + 128 * tp + 2 * hh;
                    float2 nv = *(const float2*)&shNorm[s0];
                    int t0 = 4 * tp + 2 * hh;
#pragma unroll
                    for (int u = 0; u < 2; u++) {
                        float2 f = unpack2(acc2[u][2 * tp + hh]);
                        karr[u][t0    ] = sortable_u(fmaf(-2.f, f.x, nv.x));
                        karr[u][t0 + 1] = sortable_u(fmaf(-2.f, f.y, nv.y));
                    }
                }
            }
        } else {
            float acc[2][SPL];
#pragma unroll
            for (int u = 0; u < 2; u++)
#pragma unroll
                for (int t = 0; t < SPL; t++) acc[u][t] = 0.f;
#pragma unroll 4
            for (int d = 0; d < 32; d++) {
                float xd0 = __shfl_sync(FULL, xr[0], d);
                float xd1 = __shfl_sync(FULL, xr[1], d);
#pragma unroll
                for (int t = 0; t < SPL; t++) {
                    float v = shT[d * TS + lane + 32 * t];
                    acc[0][t] = fmaf(xd0, v, acc[0][t]);
                    acc[1][t] = fmaf(xd1, v, acc[1][t]);
                }
            }
#pragma unroll
            for (int t = 0; t < SPL; t++) {
                int s = lane + 32 * t;
                float nv = shNorm[s];
#pragma unroll
                for (int u = 0; u < 2; u++)
                    karr[u][t] = sortable_u(fmaf(-2.f, acc[u][t], nv));
            }
        }

        // ---- top-8 via redux-min, interleaved over the 2 dst; gather P + max ----
        float m[2] = {-3.0e38f, -3.0e38f};

#pragma unroll
        for (int k = 0; k < 8; k++) {
#pragma unroll
            for (int u = 0; u < 2; u++) {
                unsigned bk = 0xFFFFFFFFu; int bt = 0;
#pragma unroll
                for (int t = 0; t < SPL; t++) {
                    unsigned kk = karr[u][t];
                    bool lt = kk < bk;       // first-win keeps smallest slot index on ties
                    bk = lt ? kk : bk;
                    bt = lt ? t  : bt;
                }
                unsigned gk = __reduce_min_sync(FULL, bk);
                int s = (NS == 512) ? (4 * lane + 128 * (bt >> 2) + (bt & 3))
                                    : (lane + 32 * bt);
                unsigned cand = (bk == gk) ? (unsigned)s : 0xFFFFFFFFu;
                unsigned gi = __reduce_min_sync(FULL, cand);
                bool won = (bk == gk) && ((unsigned)s == gi);
#pragma unroll
                for (int t = 0; t < SPL; t++)
                    karr[u][t] = (won && t == bt) ? 0xFFFFFFFFu : karr[u][t];

                float pj = shP[gi * 32 + lane];   // broadcast row, conflict-free
                m[u] = fmaxf(m[u], elu_f(a[u] + pj));
            }
        }

#pragma unroll
        for (int u = 0; u < 2; u++) outB[(d0 + u) * 32 + lane] = m[u];
    }
}

// merged conv for f1 (sv->trk, NS=64) and f2 (pfc->trk, NS=512).
// Long NS=512 blocks first for load balance.
__global__ void __launch_bounds__(640, 1) conv_f1f2_k(
    const float* __restrict__ enc_sv,  const float* __restrict__ enc_pfc,
    const float* __restrict__ enc_trk,
    const float* __restrict__ P_sv,    const float* __restrict__ P_pfc,
    const float* __restrict__ A_trk,
    float* __restrict__ f1, float* __restrict__ f2)
{
    extern __shared__ float sh[];
    int b = blockIdx.x;
    if (b < 256) {
        edge_conv_body<512>(enc_pfc + (size_t)b * 512 * 32,
                            enc_trk + (size_t)b * 512 * 32,
                            P_pfc   + (size_t)b * 512 * 32,
                            A_trk   + (size_t)b * 512 * 32,
                            f2      + (size_t)b * 512 * 32, sh);
    } else {
        int e = b - 256;
        edge_conv_body<64>(enc_sv  + (size_t)e * 64  * 32,
                           enc_trk + (size_t)e * 512 * 32,
                           P_sv    + (size_t)e * 64  * 32,
                           A_trk   + (size_t)e * 512 * 32,
                           f1      + (size_t)e * 512 * 32, sh);
    }
}

__global__ void __launch_bounds__(640, 1) conv_f3_k(
    const float* __restrict__ f1, const float* __restrict__ f2,
    const float* __restrict__ P_f1, const float* __restrict__ A_f2,
    float* __restrict__ f3)
{
    extern __shared__ float sh[];
    int b = blockIdx.x;
    edge_conv_body<512>(f1   + (size_t)b * 512 * 32,
                        f2   + (size_t)b * 512 * 32,
                        P_f1 + (size_t)b * 512 * 32,
                        A_f2 + (size_t)b * 512 * 32,
                        f3   + (size_t)b * 512 * 32, sh);
}

// ---------------- mean pool over 512 trk + output MLP + sigmoid ----------------
__global__ void __launch_bounds__(256) pool_out_k(
    const float* __restrict__ f3,
    const float* __restrict__ W1, const float* __restrict__ b1,
    const float* __restrict__ W2, const float* __restrict__ b2,
    float* __restrict__ outF)
{
    __shared__ float part[8][32];
    int tid = threadIdx.x, lane = tid & 31, w = tid >> 5;
    int b = blockIdx.x;
    const float* f = f3 + (size_t)b * 512 * 32;
    float s = 0.f;
    for (int r = w; r < 512; r += 8) s += f[r * 32 + lane];
    part[w][lane] = s;
    __syncthreads();
    if (w == 0) {
        float p = 0.f;
#pragma unroll
        for (int i = 0; i < 8; i++) p += part[i][lane];
        p *= (1.f / 512.f);
        float h = b1[lane];
#pragma unroll
        for (int i = 0; i < 32; i++)
            h = fmaf(__shfl_sync(FULL, p, i), W1[i * 32 + lane], h);
        h = elu_f(h);
        float z = h * W2[lane];
#pragma unroll
        for (int o = 16; o; o >>= 1) z += __shfl_xor_sync(FULL, z, o);
        if (lane == 0) {
            float t = z + b2[0];
            outF[b] = 1.f / (1.f + __expf(-t));
        }
    }
}

// ---------------- second tuple output (arange) handling ----------------
__global__ void tail_k(float* outF, int out_size) {
    int i = threadIdx.x;  // 512 threads
    if (out_size == 768) {
        if (i < 256) {
            long long* p = (long long*)(outF + 256);
            p[i] = (long long)i;
        }
    } else if (out_size > 256) {
        if (i < out_size - 256) outF[256 + i] = (float)i;
    }
}

constexpr int SMEM512 = (32 * 516 + 512 * 32 + 512) * 4;  // 133632 B

} // namespace

extern "C" void kernel_launch(void* const* d_in, const int* in_sizes, int n_in,
                              void* d_out, int out_size)
{
    const float* x_sv   = (const float*)d_in[0];
    const float* x_trk  = (const float*)d_in[1];
    const float* x_pfc  = (const float*)d_in[2];
    // d_in[3..5] = batch indices (implicit, unused)
    const float* sv_W1  = (const float*)d_in[6];
    const float* sv_b1  = (const float*)d_in[7];
    const float* sv_W2  = (const float*)d_in[8];
    const float* sv_b2  = (const float*)d_in[9];
    const float* trk_W1 = (const float*)d_in[10];
    const float* trk_b1 = (const float*)d_in[11];
    const float* trk_W2 = (const float*)d_in[12];
    const float* trk_b2 = (const float*)d_in[13];
    const float* pfc_W1 = (const float*)d_in[14];
    const float* pfc_b1 = (const float*)d_in[15];
    const float* pfc_W2 = (const float*)d_in[16];
    const float* pfc_b2 = (const float*)d_in[17];
    const float* conv_W = (const float*)d_in[18];
    const float* conv_b = (const float*)d_in[19];
    const float* out_W1 = (const float*)d_in[20];
    const float* out_b1 = (const float*)d_in[21];
    const float* out_W2 = (const float*)d_in[22];
    const float* out_b2 = (const float*)d_in[23];

    float *enc_sv, *enc_trk, *enc_pfc, *f1, *f2, *f3;
    float *P_sv, *P_pfc, *P_f1, *A_trk, *A_f2;
    cudaGetSymbolAddress((void**)&enc_sv,  g_enc_sv);
    cudaGetSymbolAddress((void**)&enc_trk, g_enc_trk);
    cudaGetSymbolAddress((void**)&enc_pfc, g_enc_pfc);
    cudaGetSymbolAddress((void**)&f1, g_f1);
    cudaGetSymbolAddress((void**)&f2, g_f2);
    cudaGetSymbolAddress((void**)&f3, g_f3);
    cudaGetSymbolAddress((void**)&P_sv,  g_P_sv);
    cudaGetSymbolAddress((void**)&P_pfc, g_P_pfc);
    cudaGetSymbolAddress((void**)&P_f1,  g_P_f1);
    cudaGetSymbolAddress((void**)&A_trk, g_A_trk);
    cudaGetSymbolAddress((void**)&A_f2,  g_A_f2);

    cudaFuncSetAttribute(conv_f1f2_k,
                         cudaFuncAttributeMaxDynamicSharedMemorySize, SMEM512);
    cudaFuncSetAttribute(conv_f3_k,
                         cudaFuncAttributeMaxDynamicSharedMemorySize, SMEM512);

    prep_w_k<<<1, 1024>>>(conv_W);

    encode_all_k<<<2176, 256>>>(
        x_trk, trk_W1, trk_b1, trk_W2, trk_b2,
        x_pfc, pfc_W1, pfc_b1, pfc_W2, pfc_b2,
        x_sv,  sv_W1,  sv_b1,  sv_W2,  sv_b2,
        enc_trk, enc_pfc, enc_sv);

    proj1_k<<<2176, 256>>>(enc_trk, enc_pfc, enc_sv, conv_b, A_trk, P_pfc, P_sv);

    conv_f1f2_k<<<512, 640, SMEM512>>>(enc_sv, enc_pfc, enc_trk,
                                       P_sv, P_pfc, A_trk, f1, f2);

    proj2_k<<<2048, 256>>>(f1, f2, conv_b, P_f1, A_f2);

    conv_f3_k<<<BQ, 640, SMEM512>>>(f1, f2, P_f1, A_f2, f3);

    pool_out_k<<<BQ, 256>>>(f3, out_W1, out_b1, out_W2, out_b2, (float*)d_out);
    if (out_size > 256) tail_k<<<1, 512>>>((float*)d_out, out_size);
}